// round 11
// baseline (speedup 1.0000x reference)
#include <cuda_runtime.h>
#include <cuda_fp16.h>
#include <cstdint>

#define N_NODES 131072
#define KNBR    27
#define FIN     3
#define FOUT    32
#define CHUNK   128
#define NCHUNKS (N_NODES / CHUNK)   // 1024

// 8 MB scratch: intermediate h (post BN+SiLU), fp16, fragment-permuted rows:
// g_h[n*32 + perm32(c)] = h[n][c] => lane c4 reads its whole m16n8k16 A-slice
// of a row as ONE contiguous 16B chunk at byte offset c4*16 of the 64B row.
__device__ __half g_h[N_NODES * FOUT];

__device__ __forceinline__ int perm32(int c) {
    return ((c >> 1) & 3) * 8 + ((c >> 3) << 1) + (c & 1);
}

__device__ __forceinline__ uint32_t f2tf32(float x) {
    uint32_t r;
    asm("cvt.rna.tf32.f32 %0, %1;" : "=r"(r) : "f"(x));
    return r;
}

__device__ __forceinline__ uint32_t smem_u32(const void* p) {
    return (uint32_t)__cvta_generic_to_shared(p);
}

__device__ __forceinline__ void cp16(uint32_t dst, const void* src) {
    asm volatile("cp.async.cg.shared.global [%0], [%1], 16;"
                 :: "r"(dst), "l"(src) : "memory");
}
// 4-byte copy with runtime src-size (0 => zero-fill the 4 bytes).
__device__ __forceinline__ void cp4(uint32_t dst, const void* src, int sz) {
    asm volatile("cp.async.ca.shared.global [%0], [%1], 4, %2;"
                 :: "r"(dst), "l"(src), "r"(sz) : "memory");
}
__device__ __forceinline__ void cp_commit() {
    asm volatile("cp.async.commit_group;" ::: "memory");
}
__device__ __forceinline__ void cp_wait3() {
    asm volatile("cp.async.wait_group 3;" ::: "memory");
}

__device__ __forceinline__ void mma_tf32(float d[4], const uint32_t a[4],
                                         const uint32_t b[2]) {
    asm volatile(
        "mma.sync.aligned.m16n8k8.row.col.f32.tf32.tf32.f32 "
        "{%0,%1,%2,%3}, {%4,%5,%6,%7}, {%8,%9}, {%0,%1,%2,%3};"
        : "+f"(d[0]), "+f"(d[1]), "+f"(d[2]), "+f"(d[3])
        : "r"(a[0]), "r"(a[1]), "r"(a[2]), "r"(a[3]),
          "r"(b[0]), "r"(b[1]));
}

__device__ __forceinline__ void mma_f16(float d[4],
                                        uint32_t a0, uint32_t a1, uint32_t a2, uint32_t a3,
                                        uint32_t b0, uint32_t b1) {
    asm volatile(
        "mma.sync.aligned.m16n8k16.row.col.f32.f16.f16.f32 "
        "{%0,%1,%2,%3}, {%4,%5,%6,%7}, {%8,%9}, {%0,%1,%2,%3};"
        : "+f"(d[0]), "+f"(d[1]), "+f"(d[2]), "+f"(d[3])
        : "r"(a0), "r"(a1), "r"(a2), "r"(a3), "r"(b0), "r"(b1));
}

// ---------------------------------------------------------------------------
// Stage 1: h = BN+SiLU( sum_k x[nbr[n,k]] @ w1[k] ), tf32 mma (K 3->8 pad).
// 256 threads, one 128-node chunk per CTA (grid=1024). Warp owns 16 nodes.
// Gathers via cp.async depth-3 pipeline into per-warp smem slots (4 slots,
// each 2 frags x 32 lanes x 4B). Lane copies exactly the 4B it consumes.
// Epilogue: per-warp smem transpose -> fp16 permuted g_h, coalesced STG.128.
// ---------------------------------------------------------------------------
#define S1_NBR   0
#define S1_W1    (CHUNK * KNBR * 4)               // 13824
#define S1_SC    (S1_W1 + KNBR * 32 * 4 * 4)      // 27648
#define S1_SH    (S1_SC + 128)                    // 27776
#define S1_STG   (S1_SH + 128)                    // 27904 (16B aligned)
#define S1_BUF   (S1_STG + 8 * 1024)              // 36096
#define S1_SMEM  (S1_BUF + 8 * 1024)              // 44288

__global__ __launch_bounds__(256) void stage1_kernel(
    const float* __restrict__ x, const int* __restrict__ nbr,
    const float* __restrict__ w1,
    const float* __restrict__ bg, const float* __restrict__ bb,
    const float* __restrict__ bm, const float* __restrict__ bv)
{
    extern __shared__ char smem[];
    int*      nbr_s = (int*)(smem + S1_NBR);
    uint32_t* w1s   = (uint32_t*)(smem + S1_W1);
    float*    sc    = (float*)(smem + S1_SC);
    float*    sh    = (float*)(smem + S1_SH);

    const int tid = threadIdx.x;
    const int nbase = blockIdx.x * CHUNK;

    for (int i = tid; i < KNBR * 32 * 4; i += 256) {
        int k = i >> 7, o = (i >> 2) & 31, c = i & 3;
        float v = (c < FIN) ? w1[(k * FIN + c) * FOUT + o] : 0.0f;
        w1s[i] = f2tf32(v);
    }
    for (int i = tid; i < CHUNK * KNBR; i += 256)
        nbr_s[i] = nbr[nbase * KNBR + i];
    if (tid < 32) {
        float s = bg[tid] * rsqrtf(bv[tid] + 1e-5f);
        sc[tid] = s;
        sh[tid] = bb[tid] - bm[tid] * s;
    }
    __syncthreads();

    const int warp = tid >> 5, lane = tid & 31;
    const int g = lane >> 2, c4 = lane & 3;
    const int* nbr_w = nbr_s + warp * 16 * KNBR;
    const uint32_t stg = smem_u32(smem + S1_STG) + warp * 1024;
    const float* stgf = (const float*)(smem + S1_STG + warp * 1024);
    const int csz = (c4 < FIN) ? 4 : 0;
    const int coff = (c4 < FIN) ? c4 : 0;
    __half* buf = (__half*)(smem + S1_BUF) + warp * 512;

    float acc[4][4];
    #pragma unroll
    for (int nf = 0; nf < 4; nf++)
        #pragma unroll
        for (int i = 0; i < 4; i++) acc[nf][i] = 0.0f;

#define ISSUE1(kk, slot) { \
    int kc = (kk); \
    if (kc < KNBR) { \
        int r0 = nbr_w[g * KNBR + kc]; \
        int r1 = nbr_w[(8 + g) * KNBR + kc]; \
        cp4(stg + (slot) * 256 + lane * 4,       x + r0 * FIN + coff, csz); \
        cp4(stg + (slot) * 256 + 128 + lane * 4, x + r1 * FIN + coff, csz); \
    } \
    cp_commit(); }

    ISSUE1(0, 0); ISSUE1(1, 1); ISSUE1(2, 2);
    #pragma unroll 1
    for (int k = 0; k < KNBR; k++) {
        ISSUE1(k + 3, (k + 3) & 3);
        cp_wait3();
        float x0 = stgf[(k & 3) * 64 + lane];
        float x1 = stgf[(k & 3) * 64 + 32 + lane];
        uint32_t a[4];
        a[0] = f2tf32(x0); a[1] = f2tf32(x1); a[2] = 0u; a[3] = 0u;
        #pragma unroll
        for (int nf = 0; nf < 4; nf++) {
            uint32_t b[2] = { w1s[((k * 32 + nf * 8 + g) << 2) + c4], 0u };
            mma_tf32(acc[nf], a, b);
        }
    }
#undef ISSUE1

    // BN + SiLU -> fp16 permuted smem tile -> coalesced 16B stores.
    #pragma unroll
    for (int nf = 0; nf < 4; nf++)
        #pragma unroll
        for (int i = 0; i < 4; i++) {
            int o  = nf * 8 + 2 * c4 + (i & 1);
            int nl = g + ((i >> 1) << 3);
            float v = acc[nf][i] * sc[o] + sh[o];
            float s = v * (1.0f / (1.0f + __expf(-v)));
            buf[nl * 32 + perm32(o)] = __float2half_rn(s);
        }
    __syncwarp();
    uint4* dst = (uint4*)(g_h + (size_t)(nbase + warp * 16) * FOUT);
    const uint4* src = (const uint4*)buf;
    dst[lane] = src[lane];
    dst[32 + lane] = src[32 + lane];
}

// ---------------------------------------------------------------------------
// Stage 2: fp16 m16n8k16 gather-GEMM over g_h + point branch + fused output.
// 256 threads, persistent static stride over 1024 chunks of 128 nodes.
// h gathers via cp.async.cg (16B) depth-3 pipeline into per-warp smem slots
// (4 slots x 2 frags x 32 lanes x 16B = 4KB/warp). Lane copies exactly the
// 16B A-fragment slice it consumes -> no barriers in the hot loop.
// w2 in smem, fragment-permuted: conflict-free LDS.128.
// ---------------------------------------------------------------------------
#define S2_W2   0                             // 55296 (16B aligned)
#define S2_NBR  (KNBR * 32 * 32 * 2)          // 55296
#define S2_MW   (S2_NBR + CHUNK * KNBR * 4)   // 69120
#define S2_PA   (S2_MW + 96 * 4)              // 69504
#define S2_PB   (S2_PA + 128)                 // 69632
#define S2_STG  (S2_PB + 128)                 // 69760 (16B aligned)
#define S2_SMEM (S2_STG + 8 * 4096)           // 102528

__global__ __launch_bounds__(256) void stage2_kernel(
    const int* __restrict__ nbr,
    const float* __restrict__ w2,
    const float* __restrict__ zf,
    const float* __restrict__ mlpw, const float* __restrict__ mlpb,
    const float* __restrict__ mg, const float* __restrict__ mb2,
    const float* __restrict__ mm, const float* __restrict__ mv,
    float* __restrict__ out)
{
    extern __shared__ char smem[];
    __half*    w2h   = (__half*)(smem + S2_W2);
    int*       nbr_s = (int*)(smem + S2_NBR);
    float*     mw_s  = (float*)(smem + S2_MW);
    float*     pA    = (float*)(smem + S2_PA);
    float*     pB    = (float*)(smem + S2_PB);

    const int tid = threadIdx.x;

    for (int i = tid; i < KNBR * FOUT * FOUT; i += 256) {
        int k = i >> 10, c = (i >> 5) & 31, o = i & 31;
        w2h[(k * 32 + o) * 32 + perm32(c)] = __float2half_rn(__ldg(w2 + i));
    }
    for (int i = tid; i < FIN * FOUT; i += 256) mw_s[i] = mlpw[i];
    if (tid < 32) {
        float s = mg[tid] * rsqrtf(mv[tid] + 1e-5f);
        pA[tid] = s;
        pB[tid] = mlpb[tid] * s + mb2[tid] - mm[tid] * s;
    }

    const char* hB = (const char*)g_h;
    const uint4* w2v = (const uint4*)w2h;
    const int warp = tid >> 5, lane = tid & 31;
    const int g = lane >> 2, c4 = lane & 3;
    const int* nbr_w = nbr_s + warp * 16 * KNBR;
    const uint32_t stg = smem_u32(smem + S2_STG) + warp * 4096;
    const uint4* stgv = (const uint4*)(smem + S2_STG + warp * 4096);

#define ISSUE2(kk, slot) { \
    int kc = (kk); \
    if (kc < KNBR) { \
        int r0 = nbr_w[g * KNBR + kc]; \
        int r1 = nbr_w[(8 + g) * KNBR + kc]; \
        cp16(stg + (slot) * 1024 + lane * 16,       hB + ((size_t)r0 << 6) + (c4 << 4)); \
        cp16(stg + (slot) * 1024 + 512 + lane * 16, hB + ((size_t)r1 << 6) + (c4 << 4)); \
    } \
    cp_commit(); }

    for (int chunk = blockIdx.x; chunk < NCHUNKS; chunk += gridDim.x) {
        const int nbase = chunk * CHUNK;
        __syncthreads();                 // protect nbr_s reuse (and w2h init)
        for (int i = tid; i < CHUNK * KNBR; i += 256)
            nbr_s[i] = nbr[nbase * KNBR + i];
        __syncthreads();

        float acc[4][4];
        #pragma unroll
        for (int nf = 0; nf < 4; nf++)
            #pragma unroll
            for (int i = 0; i < 4; i++) acc[nf][i] = 0.0f;

        ISSUE2(0, 0); ISSUE2(1, 1); ISSUE2(2, 2);
        #pragma unroll 1
        for (int k = 0; k < KNBR; k++) {
            ISSUE2(k + 3, (k + 3) & 3);
            cp_wait3();
            uint4 A0 = stgv[(k & 3) * 64 + lane];
            uint4 A1 = stgv[(k & 3) * 64 + 32 + lane];
            #pragma unroll
            for (int nf = 0; nf < 4; nf++) {
                uint4 W = w2v[((k * 32 + nf * 8 + g) << 2) + c4];
                mma_f16(acc[nf], A0.x, A1.x, A0.y, A1.y, W.x, W.y);
                mma_f16(acc[nf], A0.z, A1.z, A0.w, A1.w, W.z, W.w);
            }
        }

        // Epilogue: point branch + fuse; write both output copies.
        {
            int n0 = nbase + warp * 16 + g;
            float z00 = zf[n0 * 3], z01 = zf[n0 * 3 + 1], z02 = zf[n0 * 3 + 2];
            float z10 = zf[(n0 + 8) * 3], z11 = zf[(n0 + 8) * 3 + 1], z12 = zf[(n0 + 8) * 3 + 2];
            #pragma unroll
            for (int nf = 0; nf < 4; nf++) {
                int o0 = nf * 8 + 2 * c4;
                float w0a = mw_s[o0],     w1a = mw_s[32 + o0],     w2a = mw_s[64 + o0];
                float w0b = mw_s[o0 + 1], w1b = mw_s[32 + o0 + 1], w2b = mw_s[64 + o0 + 1];
                float sA0 = pA[o0], sB0 = pB[o0], sA1 = pA[o0 + 1], sB1 = pB[o0 + 1];

                float d0 = z00 * w0a + z01 * w1a + z02 * w2a;
                float d1 = z00 * w0b + z01 * w1b + z02 * w2b;
                float e0 = z10 * w0a + z11 * w1a + z12 * w2a;
                float e1 = z10 * w0b + z11 * w1b + z12 * w2b;

                float2 lo, hi;
                lo.x = acc[nf][0] + fmaxf(d0 * sA0 + sB0, 0.0f);
                lo.y = acc[nf][1] + fmaxf(d1 * sA1 + sB1, 0.0f);
                hi.x = acc[nf][2] + fmaxf(e0 * sA0 + sB0, 0.0f);
                hi.y = acc[nf][3] + fmaxf(e1 * sA1 + sB1, 0.0f);

                size_t half = (size_t)N_NODES * FOUT;
                *(float2*)(out + (size_t)n0 * FOUT + o0)              = lo;
                *(float2*)(out + half + (size_t)n0 * FOUT + o0)       = lo;
                *(float2*)(out + (size_t)(n0 + 8) * FOUT + o0)        = hi;
                *(float2*)(out + half + (size_t)(n0 + 8) * FOUT + o0) = hi;
            }
        }
    }
#undef ISSUE2
}

// ---------------------------------------------------------------------------

extern "C" void kernel_launch(void* const* d_in, const int* in_sizes, int n_in,
                              void* d_out, int out_size) {
    (void)in_sizes; (void)n_in; (void)out_size;
    const float* x    = (const float*)d_in[0];
    const float* z    = (const float*)d_in[1];
    const int*   nbr  = (const int*)  d_in[2];
    const float* w1   = (const float*)d_in[3];
    const float* bg   = (const float*)d_in[4];
    const float* bb   = (const float*)d_in[5];
    const float* bm   = (const float*)d_in[6];
    const float* bv   = (const float*)d_in[7];
    const float* w2   = (const float*)d_in[8];
    const float* mlpw = (const float*)d_in[9];
    const float* mlpb = (const float*)d_in[10];
    const float* mg   = (const float*)d_in[11];
    const float* mb2  = (const float*)d_in[12];
    const float* mm   = (const float*)d_in[13];
    const float* mv   = (const float*)d_in[14];
    float* out = (float*)d_out;

    cudaFuncSetAttribute(stage1_kernel, cudaFuncAttributeMaxDynamicSharedMemorySize, S1_SMEM);
    cudaFuncSetAttribute(stage2_kernel, cudaFuncAttributeMaxDynamicSharedMemorySize, S2_SMEM);

    stage1_kernel<<<NCHUNKS, 256, S1_SMEM>>>(x, nbr, w1, bg, bb, bm, bv);
    stage2_kernel<<<296, 256, S2_SMEM>>>(nbr, w2, z, mlpw, mlpb, mg, mb2, mm, mv, out);
}

// round 13
// speedup vs baseline: 1.1627x; 1.1627x over previous
#include <cuda_runtime.h>
#include <cuda_fp16.h>
#include <cstdint>

#define N_NODES 131072
#define KNBR    27
#define FIN     3
#define FOUT    32
#define CHUNK   256
#define NCHUNKS (N_NODES / CHUNK)   // 512

// Scratch: h (fp16, fragment-permuted rows, 8MB) and fp16 permuted w2 (55KB,
// L1-resident broadcast weight table).
// g_h[n*32 + perm32(c)] = h[n][c] => lane c4 reads its whole m16n8k16 A-slice
// of a row as ONE contiguous 16B chunk at byte offset c4*16 of the 64B row.
__device__ __half g_h[N_NODES * FOUT];
__device__ __half g_w2h[KNBR * FOUT * FOUT];

__device__ __forceinline__ int perm32(int c) {
    return ((c >> 1) & 3) * 8 + ((c >> 3) << 1) + (c & 1);
}

__device__ __forceinline__ uint32_t f2tf32(float x) {
    uint32_t r;
    asm("cvt.rna.tf32.f32 %0, %1;" : "=r"(r) : "f"(x));
    return r;
}

__device__ __forceinline__ uint32_t smem_u32(const void* p) {
    return (uint32_t)__cvta_generic_to_shared(p);
}

__device__ __forceinline__ void cp16(uint32_t dst, const void* src) {
    asm volatile("cp.async.cg.shared.global [%0], [%1], 16;"
                 :: "r"(dst), "l"(src) : "memory");
}
// 4-byte copy with runtime src-size (0 => zero-fill the 4 bytes).
__device__ __forceinline__ void cp4(uint32_t dst, const void* src, int sz) {
    asm volatile("cp.async.ca.shared.global [%0], [%1], 4, %2;"
                 :: "r"(dst), "l"(src), "r"(sz) : "memory");
}
__device__ __forceinline__ void cp_commit() {
    asm volatile("cp.async.commit_group;" ::: "memory");
}
__device__ __forceinline__ void cp_wait3() {
    asm volatile("cp.async.wait_group 3;" ::: "memory");
}

__device__ __forceinline__ void mma_tf32(float d[4], const uint32_t a[4],
                                         const uint32_t b[2]) {
    asm volatile(
        "mma.sync.aligned.m16n8k8.row.col.f32.tf32.tf32.f32 "
        "{%0,%1,%2,%3}, {%4,%5,%6,%7}, {%8,%9}, {%0,%1,%2,%3};"
        : "+f"(d[0]), "+f"(d[1]), "+f"(d[2]), "+f"(d[3])
        : "r"(a[0]), "r"(a[1]), "r"(a[2]), "r"(a[3]),
          "r"(b[0]), "r"(b[1]));
}

__device__ __forceinline__ void mma_f16(float d[4],
                                        uint32_t a0, uint32_t a1, uint32_t a2, uint32_t a3,
                                        uint32_t b0, uint32_t b1) {
    asm volatile(
        "mma.sync.aligned.m16n8k16.row.col.f32.f16.f16.f32 "
        "{%0,%1,%2,%3}, {%4,%5,%6,%7}, {%8,%9}, {%0,%1,%2,%3};"
        : "+f"(d[0]), "+f"(d[1]), "+f"(d[2]), "+f"(d[3])
        : "r"(a0), "r"(a1), "r"(a2), "r"(a3), "r"(b0), "r"(b1));
}

// ---------------------------------------------------------------------------
// Stage 1: h = BN+SiLU( sum_k x[nbr[n,k]] @ w1[k] ), tf32 mma (K 3->8 pad).
// 512 threads, one 256-node chunk per CTA (grid=512, 2 CTAs/SM). Warp owns
// 16 nodes. Gathers via cp.async depth-3 pipeline into per-warp smem slots.
// Blocks 0..26 additionally convert w2[k] into g_w2h (used by stage 2).
// Epilogue: per-warp smem transpose -> fp16 permuted g_h, coalesced STG.128.
// ---------------------------------------------------------------------------
#define S1_NBR   0
#define S1_W1    (CHUNK * KNBR * 4)               // 27648
#define S1_SC    (S1_W1 + KNBR * 32 * 4 * 4)      // 41472
#define S1_SH    (S1_SC + 128)                    // 41600
#define S1_STG   (S1_SH + 128)                    // 41728 (16B aligned)
#define S1_BUF   (S1_STG + 16 * 1024)             // 58112
#define S1_SMEM  (S1_BUF + 16 * 1024)             // 74496

__global__ __launch_bounds__(512, 2) void stage1_kernel(
    const float* __restrict__ x, const int* __restrict__ nbr,
    const float* __restrict__ w1, const float* __restrict__ w2,
    const float* __restrict__ bg, const float* __restrict__ bb,
    const float* __restrict__ bm, const float* __restrict__ bv)
{
    extern __shared__ char smem[];
    int*      nbr_s = (int*)(smem + S1_NBR);
    uint32_t* w1s   = (uint32_t*)(smem + S1_W1);
    float*    sc    = (float*)(smem + S1_SC);
    float*    sh    = (float*)(smem + S1_SH);

    const int tid = threadIdx.x;
    const int nbase = blockIdx.x * CHUNK;

    // Side job: blocks 0..26 convert w2[k] -> g_w2h (fp16, fragment-permuted).
    if (blockIdx.x < KNBR) {
        int k = blockIdx.x;
        for (int i = tid; i < FOUT * FOUT; i += 512) {
            int c = i >> 5, o = i & 31;
            g_w2h[(k * 32 + o) * 32 + perm32(c)] =
                __float2half_rn(w2[k * 1024 + c * 32 + o]);
        }
    }

    for (int i = tid; i < KNBR * 32 * 4; i += 512) {
        int k = i >> 7, o = (i >> 2) & 31, c = i & 3;
        float v = (c < FIN) ? w1[(k * FIN + c) * FOUT + o] : 0.0f;
        w1s[i] = f2tf32(v);
    }
    for (int i = tid; i < CHUNK * KNBR; i += 512)
        nbr_s[i] = nbr[nbase * KNBR + i];
    if (tid < 32) {
        float s = bg[tid] * rsqrtf(bv[tid] + 1e-5f);
        sc[tid] = s;
        sh[tid] = bb[tid] - bm[tid] * s;
    }
    __syncthreads();

    const int warp = tid >> 5, lane = tid & 31;
    const int g = lane >> 2, c4 = lane & 3;
    const int* nbr_w = nbr_s + warp * 16 * KNBR;
    const uint32_t stg = smem_u32(smem + S1_STG) + warp * 1024;
    const float* stgf = (const float*)(smem + S1_STG + warp * 1024);
    const int csz = (c4 < FIN) ? 4 : 0;
    const int coff = (c4 < FIN) ? c4 : 0;
    __half* buf = (__half*)(smem + S1_BUF) + warp * 512;

    float acc[4][4];
    #pragma unroll
    for (int nf = 0; nf < 4; nf++)
        #pragma unroll
        for (int i = 0; i < 4; i++) acc[nf][i] = 0.0f;

#define ISSUE1(kk, slot) { \
    int kc = (kk); \
    if (kc < KNBR) { \
        int r0 = nbr_w[g * KNBR + kc]; \
        int r1 = nbr_w[(8 + g) * KNBR + kc]; \
        cp4(stg + (slot) * 256 + lane * 4,       x + r0 * FIN + coff, csz); \
        cp4(stg + (slot) * 256 + 128 + lane * 4, x + r1 * FIN + coff, csz); \
    } \
    cp_commit(); }

    ISSUE1(0, 0); ISSUE1(1, 1); ISSUE1(2, 2);
    #pragma unroll 1
    for (int k = 0; k < KNBR; k++) {
        ISSUE1(k + 3, (k + 3) & 3);
        cp_wait3();
        float x0 = stgf[(k & 3) * 64 + lane];
        float x1 = stgf[(k & 3) * 64 + 32 + lane];
        uint32_t a[4];
        a[0] = f2tf32(x0); a[1] = f2tf32(x1); a[2] = 0u; a[3] = 0u;
        #pragma unroll
        for (int nf = 0; nf < 4; nf++) {
            uint32_t b[2] = { w1s[((k * 32 + nf * 8 + g) << 2) + c4], 0u };
            mma_tf32(acc[nf], a, b);
        }
    }
#undef ISSUE1

    // BN + SiLU -> fp16 permuted smem tile -> coalesced 16B stores.
    #pragma unroll
    for (int nf = 0; nf < 4; nf++)
        #pragma unroll
        for (int i = 0; i < 4; i++) {
            int o  = nf * 8 + 2 * c4 + (i & 1);
            int nl = g + ((i >> 1) << 3);
            float v = acc[nf][i] * sc[o] + sh[o];
            float s = v * (1.0f / (1.0f + __expf(-v)));
            buf[nl * 32 + perm32(o)] = __float2half_rn(s);
        }
    __syncwarp();
    uint4* dst = (uint4*)(g_h + (size_t)(nbase + warp * 16) * FOUT);
    const uint4* src = (const uint4*)buf;
    dst[lane] = src[lane];
    dst[32 + lane] = src[32 + lane];
}

// ---------------------------------------------------------------------------
// Stage 2: fp16 m16n8k16 gather-GEMM over g_h + point branch + fused output.
// 512 threads, one 256-node chunk per CTA (grid=512, non-persistent -> HW
// load balancing), 2 CTAs/SM. h gathers via cp.async.cg (16B) depth-3
// pipeline into per-warp smem slots; lane copies exactly the 16B A-fragment
// slice it consumes -> no barriers in the hot loop. W fragments read from
// g_w2h via LDG.128 (55KB table, L1-resident broadcast).
// ---------------------------------------------------------------------------
#define S2_NBR  0                             // 27648
#define S2_MW   (CHUNK * KNBR * 4)            // 27648
#define S2_PA   (S2_MW + 96 * 4)              // 28032
#define S2_PB   (S2_PA + 128)                 // 28160
#define S2_STG  (S2_PB + 128)                 // 28288 (16B aligned)
#define S2_SMEM (S2_STG + 16 * 4096)          // 93824

__global__ __launch_bounds__(512, 2) void stage2_kernel(
    const int* __restrict__ nbr,
    const float* __restrict__ zf,
    const float* __restrict__ mlpw, const float* __restrict__ mlpb,
    const float* __restrict__ mg, const float* __restrict__ mb2,
    const float* __restrict__ mm, const float* __restrict__ mv,
    float* __restrict__ out)
{
    extern __shared__ char smem[];
    int*       nbr_s = (int*)(smem + S2_NBR);
    float*     mw_s  = (float*)(smem + S2_MW);
    float*     pA    = (float*)(smem + S2_PA);
    float*     pB    = (float*)(smem + S2_PB);

    const int tid = threadIdx.x;
    const int nbase = blockIdx.x * CHUNK;

    for (int i = tid; i < CHUNK * KNBR; i += 512)
        nbr_s[i] = nbr[nbase * KNBR + i];
    for (int i = tid; i < FIN * FOUT; i += 512) mw_s[i] = mlpw[i];
    if (tid < 32) {
        float s = mg[tid] * rsqrtf(mv[tid] + 1e-5f);
        pA[tid] = s;
        pB[tid] = mlpb[tid] * s + mb2[tid] - mm[tid] * s;
    }
    __syncthreads();

    const char*  hB   = (const char*)g_h;
    const uint4* w2v  = (const uint4*)g_w2h;
    const int warp = tid >> 5, lane = tid & 31;
    const int g = lane >> 2, c4 = lane & 3;
    const int* nbr_w = nbr_s + warp * 16 * KNBR;
    const uint32_t stg = smem_u32(smem + S2_STG) + warp * 4096;
    const uint4* stgv = (const uint4*)(smem + S2_STG + warp * 4096);

    float acc[4][4];
    #pragma unroll
    for (int nf = 0; nf < 4; nf++)
        #pragma unroll
        for (int i = 0; i < 4; i++) acc[nf][i] = 0.0f;

#define ISSUE2(kk, slot) { \
    int kc = (kk); \
    if (kc < KNBR) { \
        int r0 = nbr_w[g * KNBR + kc]; \
        int r1 = nbr_w[(8 + g) * KNBR + kc]; \
        cp16(stg + (slot) * 1024 + lane * 16,       hB + ((size_t)r0 << 6) + (c4 << 4)); \
        cp16(stg + (slot) * 1024 + 512 + lane * 16, hB + ((size_t)r1 << 6) + (c4 << 4)); \
    } \
    cp_commit(); }

    ISSUE2(0, 0); ISSUE2(1, 1); ISSUE2(2, 2);
    #pragma unroll 1
    for (int k = 0; k < KNBR; k++) {
        ISSUE2(k + 3, (k + 3) & 3);
        cp_wait3();
        uint4 A0 = stgv[(k & 3) * 64 + lane];
        uint4 A1 = stgv[(k & 3) * 64 + 32 + lane];
        #pragma unroll
        for (int nf = 0; nf < 4; nf++) {
            uint4 W = __ldg(w2v + ((k * 32 + nf * 8 + g) << 2) + c4);
            mma_f16(acc[nf], A0.x, A1.x, A0.y, A1.y, W.x, W.y);
            mma_f16(acc[nf], A0.z, A1.z, A0.w, A1.w, W.z, W.w);
        }
    }
#undef ISSUE2

    // Epilogue: point branch + fuse; write both output copies.
    {
        int n0 = nbase + warp * 16 + g;
        float z00 = zf[n0 * 3], z01 = zf[n0 * 3 + 1], z02 = zf[n0 * 3 + 2];
        float z10 = zf[(n0 + 8) * 3], z11 = zf[(n0 + 8) * 3 + 1], z12 = zf[(n0 + 8) * 3 + 2];
        #pragma unroll
        for (int nf = 0; nf < 4; nf++) {
            int o0 = nf * 8 + 2 * c4;
            float w0a = mw_s[o0],     w1a = mw_s[32 + o0],     w2a = mw_s[64 + o0];
            float w0b = mw_s[o0 + 1], w1b = mw_s[32 + o0 + 1], w2b = mw_s[64 + o0 + 1];
            float sA0 = pA[o0], sB0 = pB[o0], sA1 = pA[o0 + 1], sB1 = pB[o0 + 1];

            float d0 = z00 * w0a + z01 * w1a + z02 * w2a;
            float d1 = z00 * w0b + z01 * w1b + z02 * w2b;
            float e0 = z10 * w0a + z11 * w1a + z12 * w2a;
            float e1 = z10 * w0b + z11 * w1b + z12 * w2b;

            float2 lo, hi;
            lo.x = acc[nf][0] + fmaxf(d0 * sA0 + sB0, 0.0f);
            lo.y = acc[nf][1] + fmaxf(d1 * sA1 + sB1, 0.0f);
            hi.x = acc[nf][2] + fmaxf(e0 * sA0 + sB0, 0.0f);
            hi.y = acc[nf][3] + fmaxf(e1 * sA1 + sB1, 0.0f);

            size_t half = (size_t)N_NODES * FOUT;
            *(float2*)(out + (size_t)n0 * FOUT + o0)              = lo;
            *(float2*)(out + half + (size_t)n0 * FOUT + o0)       = lo;
            *(float2*)(out + (size_t)(n0 + 8) * FOUT + o0)        = hi;
            *(float2*)(out + half + (size_t)(n0 + 8) * FOUT + o0) = hi;
        }
    }
}

// ---------------------------------------------------------------------------

extern "C" void kernel_launch(void* const* d_in, const int* in_sizes, int n_in,
                              void* d_out, int out_size) {
    (void)in_sizes; (void)n_in; (void)out_size;
    const float* x    = (const float*)d_in[0];
    const float* z    = (const float*)d_in[1];
    const int*   nbr  = (const int*)  d_in[2];
    const float* w1   = (const float*)d_in[3];
    const float* bg   = (const float*)d_in[4];
    const float* bb   = (const float*)d_in[5];
    const float* bm   = (const float*)d_in[6];
    const float* bv   = (const float*)d_in[7];
    const float* w2   = (const float*)d_in[8];
    const float* mlpw = (const float*)d_in[9];
    const float* mlpb = (const float*)d_in[10];
    const float* mg   = (const float*)d_in[11];
    const float* mb2  = (const float*)d_in[12];
    const float* mm   = (const float*)d_in[13];
    const float* mv   = (const float*)d_in[14];
    float* out = (float*)d_out;

    cudaFuncSetAttribute(stage1_kernel, cudaFuncAttributeMaxDynamicSharedMemorySize, S1_SMEM);
    cudaFuncSetAttribute(stage2_kernel, cudaFuncAttributeMaxDynamicSharedMemorySize, S2_SMEM);

    stage1_kernel<<<NCHUNKS, 512, S1_SMEM>>>(x, nbr, w1, w2, bg, bb, bm, bv);
    stage2_kernel<<<NCHUNKS, 512, S2_SMEM>>>(nbr, z, mlpw, mlpb, mg, mb2, mm, mv, out);
}

// round 14
// speedup vs baseline: 1.1729x; 1.0087x over previous
#include <cuda_runtime.h>
#include <cuda_fp16.h>
#include <cstdint>

#define N_NODES 131072
#define KNBR    27
#define FIN     3
#define FOUT    32
#define CHUNK   256
#define NCHUNKS (N_NODES / CHUNK)   // 512

// Scratch: h (fp16, fragment-permuted rows, 8MB) and fp16 permuted w2 (55KB,
// L1-resident broadcast weight table).
// g_h[n*32 + perm32(c)] = h[n][c] => lane c4 reads its whole m16n8k16 A-slice
// of a row as ONE contiguous 16B chunk at byte offset c4*16 of the 64B row.
__device__ __half g_h[N_NODES * FOUT];
__device__ __half g_w2h[KNBR * FOUT * FOUT];

__device__ __forceinline__ int perm32(int c) {
    return ((c >> 1) & 3) * 8 + ((c >> 3) << 1) + (c & 1);
}

__device__ __forceinline__ uint32_t f2tf32(float x) {
    uint32_t r;
    asm("cvt.rna.tf32.f32 %0, %1;" : "=r"(r) : "f"(x));
    return r;
}

__device__ __forceinline__ uint32_t smem_u32(const void* p) {
    return (uint32_t)__cvta_generic_to_shared(p);
}

__device__ __forceinline__ void cp16(uint32_t dst, const void* src) {
    asm volatile("cp.async.cg.shared.global [%0], [%1], 16;"
                 :: "r"(dst), "l"(src) : "memory");
}
// 4-byte copy with runtime src-size (0 => zero-fill the 4 bytes).
__device__ __forceinline__ void cp4(uint32_t dst, const void* src, int sz) {
    asm volatile("cp.async.ca.shared.global [%0], [%1], 4, %2;"
                 :: "r"(dst), "l"(src), "r"(sz) : "memory");
}
__device__ __forceinline__ void cp_commit() {
    asm volatile("cp.async.commit_group;" ::: "memory");
}
__device__ __forceinline__ void cp_wait5() {
    asm volatile("cp.async.wait_group 5;" ::: "memory");
}

__device__ __forceinline__ void mma_tf32(float d[4], const uint32_t a[4],
                                         const uint32_t b[2]) {
    asm volatile(
        "mma.sync.aligned.m16n8k8.row.col.f32.tf32.tf32.f32 "
        "{%0,%1,%2,%3}, {%4,%5,%6,%7}, {%8,%9}, {%0,%1,%2,%3};"
        : "+f"(d[0]), "+f"(d[1]), "+f"(d[2]), "+f"(d[3])
        : "r"(a[0]), "r"(a[1]), "r"(a[2]), "r"(a[3]),
          "r"(b[0]), "r"(b[1]));
}

__device__ __forceinline__ void mma_f16(float d[4],
                                        uint32_t a0, uint32_t a1, uint32_t a2, uint32_t a3,
                                        uint32_t b0, uint32_t b1) {
    asm volatile(
        "mma.sync.aligned.m16n8k16.row.col.f32.f16.f16.f32 "
        "{%0,%1,%2,%3}, {%4,%5,%6,%7}, {%8,%9}, {%0,%1,%2,%3};"
        : "+f"(d[0]), "+f"(d[1]), "+f"(d[2]), "+f"(d[3])
        : "r"(a0), "r"(a1), "r"(a2), "r"(a3), "r"(b0), "r"(b1));
}

// ---------------------------------------------------------------------------
// Stage 1: h = BN+SiLU( sum_k x[nbr[n,k]] @ w1[k] ), tf32 mma (K 3->8 pad).
// 512 threads, one 256-node chunk per CTA (grid=512, 2 CTAs/SM). Warp owns
// 16 nodes. Gathers via cp.async depth-6 pipeline into per-warp smem slots;
// indices via __ldg (contiguous per-row walk, L1-hit after first touch).
// Blocks 0..26 additionally convert w2[k] into g_w2h (used by stage 2).
// Epilogue: per-warp smem transpose -> fp16 permuted g_h, coalesced STG.128.
// ---------------------------------------------------------------------------
#define S1_W1    0                                // 13824
#define S1_SC    (KNBR * 32 * 4 * 4)              // 13824
#define S1_SH    (S1_SC + 128)                    // 13952
#define S1_STG   (S1_SH + 128)                    // 14080 (16B aligned)
#define S1_BUF   (S1_STG + 16 * 1536)             // 38656
#define S1_SMEM  (S1_BUF + 16 * 1024)             // 55040

__global__ __launch_bounds__(512, 2) void stage1_kernel(
    const float* __restrict__ x, const int* __restrict__ nbr,
    const float* __restrict__ w1, const float* __restrict__ w2,
    const float* __restrict__ bg, const float* __restrict__ bb,
    const float* __restrict__ bm, const float* __restrict__ bv)
{
    extern __shared__ char smem[];
    uint32_t* w1s = (uint32_t*)(smem + S1_W1);
    float*    sc  = (float*)(smem + S1_SC);
    float*    sh  = (float*)(smem + S1_SH);

    const int tid = threadIdx.x;
    const int nbase = blockIdx.x * CHUNK;

    // Side job: blocks 0..26 convert w2[k] -> g_w2h (fp16, fragment-permuted).
    if (blockIdx.x < KNBR) {
        int k = blockIdx.x;
        for (int i = tid; i < FOUT * FOUT; i += 512) {
            int c = i >> 5, o = i & 31;
            g_w2h[(k * 32 + o) * 32 + perm32(c)] =
                __float2half_rn(w2[k * 1024 + c * 32 + o]);
        }
    }

    for (int i = tid; i < KNBR * 32 * 4; i += 512) {
        int k = i >> 7, o = (i >> 2) & 31, c = i & 3;
        float v = (c < FIN) ? w1[(k * FIN + c) * FOUT + o] : 0.0f;
        w1s[i] = f2tf32(v);
    }
    if (tid < 32) {
        float s = bg[tid] * rsqrtf(bv[tid] + 1e-5f);
        sc[tid] = s;
        sh[tid] = bb[tid] - bm[tid] * s;
    }
    __syncthreads();

    const int warp = tid >> 5, lane = tid & 31;
    const int g = lane >> 2, c4 = lane & 3;
    const int* nbrp0 = nbr + (size_t)(nbase + warp * 16 + g) * KNBR;
    const int* nbrp1 = nbrp0 + 8 * KNBR;
    const uint32_t stg = smem_u32(smem + S1_STG) + warp * 1536;
    const float* stgf = (const float*)(smem + S1_STG + warp * 1536);
    const int csz = (c4 < FIN) ? 4 : 0;
    const int coff = (c4 < FIN) ? c4 : 0;
    __half* buf = (__half*)(smem + S1_BUF) + warp * 512;

    float acc[4][4];
    #pragma unroll
    for (int nf = 0; nf < 4; nf++)
        #pragma unroll
        for (int i = 0; i < 4; i++) acc[nf][i] = 0.0f;

#define ISSUE1(kk, slot) { \
    int kc = (kk); \
    if (kc < KNBR) { \
        int r0 = __ldg(nbrp0 + kc); \
        int r1 = __ldg(nbrp1 + kc); \
        cp4(stg + (slot) * 256 + lane * 4,       x + r0 * FIN + coff, csz); \
        cp4(stg + (slot) * 256 + 128 + lane * 4, x + r1 * FIN + coff, csz); \
    } \
    cp_commit(); }

    ISSUE1(0, 0); ISSUE1(1, 1); ISSUE1(2, 2); ISSUE1(3, 3); ISSUE1(4, 4);
    int su = 0, si = 5;
    #pragma unroll 1
    for (int k = 0; k < KNBR; k++) {
        ISSUE1(k + 5, si);
        cp_wait5();
        float x0 = stgf[su * 64 + lane];
        float x1 = stgf[su * 64 + 32 + lane];
        uint32_t a[4];
        a[0] = f2tf32(x0); a[1] = f2tf32(x1); a[2] = 0u; a[3] = 0u;
        #pragma unroll
        for (int nf = 0; nf < 4; nf++) {
            uint32_t b[2] = { w1s[((k * 32 + nf * 8 + g) << 2) + c4], 0u };
            mma_tf32(acc[nf], a, b);
        }
        if (++su == 6) su = 0;
        if (++si == 6) si = 0;
    }
#undef ISSUE1

    // BN + SiLU -> fp16 permuted smem tile -> coalesced 16B stores.
    #pragma unroll
    for (int nf = 0; nf < 4; nf++)
        #pragma unroll
        for (int i = 0; i < 4; i++) {
            int o  = nf * 8 + 2 * c4 + (i & 1);
            int nl = g + ((i >> 1) << 3);
            float v = acc[nf][i] * sc[o] + sh[o];
            float s = v * (1.0f / (1.0f + __expf(-v)));
            buf[nl * 32 + perm32(o)] = __float2half_rn(s);
        }
    __syncwarp();
    uint4* dst = (uint4*)(g_h + (size_t)(nbase + warp * 16) * FOUT);
    const uint4* src = (const uint4*)buf;
    dst[lane] = src[lane];
    dst[32 + lane] = src[32 + lane];
}

// ---------------------------------------------------------------------------
// Stage 2: fp16 m16n8k16 gather-GEMM over g_h + point branch + fused output.
// 512 threads, one 256-node chunk per CTA (grid=512, single wave), 2 CTAs/SM.
// h gathers via cp.async.cg (16B) depth-6 pipeline into per-warp smem slots
// (6 slots x 1KB). Indices via __ldg (per-row contiguous walk -> L1 hits).
// No block barriers in the hot loop. W fragments from g_w2h via LDG.128
// (55KB table, L1-resident broadcast).
// ---------------------------------------------------------------------------
#define S2_MW   0                             // 384B
#define S2_PA   (S2_MW + 96 * 4)              // 384
#define S2_PB   (S2_PA + 128)                 // 512
#define S2_STG  1024                          // 16B aligned
#define S2_SMEM (S2_STG + 16 * 6144)          // 99328

__global__ __launch_bounds__(512, 2) void stage2_kernel(
    const int* __restrict__ nbr,
    const float* __restrict__ zf,
    const float* __restrict__ mlpw, const float* __restrict__ mlpb,
    const float* __restrict__ mg, const float* __restrict__ mb2,
    const float* __restrict__ mm, const float* __restrict__ mv,
    float* __restrict__ out)
{
    extern __shared__ char smem[];
    float* mw_s = (float*)(smem + S2_MW);
    float* pA   = (float*)(smem + S2_PA);
    float* pB   = (float*)(smem + S2_PB);

    const int tid = threadIdx.x;
    const int nbase = blockIdx.x * CHUNK;

    for (int i = tid; i < FIN * FOUT; i += 512) mw_s[i] = mlpw[i];
    if (tid < 32) {
        float s = mg[tid] * rsqrtf(mv[tid] + 1e-5f);
        pA[tid] = s;
        pB[tid] = mlpb[tid] * s + mb2[tid] - mm[tid] * s;
    }
    __syncthreads();

    const int warp = tid >> 5, lane = tid & 31;
    const int g = lane >> 2, c4 = lane & 3;
    const char*  hBc  = (const char*)g_h + (c4 << 4);
    const uint4* w2v  = (const uint4*)g_w2h;
    const int* nbrp0 = nbr + (size_t)(nbase + warp * 16 + g) * KNBR;
    const int* nbrp1 = nbrp0 + 8 * KNBR;
    const uint32_t stg = smem_u32(smem + S2_STG) + warp * 6144;
    const uint4* stgv = (const uint4*)(smem + S2_STG + warp * 6144);

    float acc[4][4];
    #pragma unroll
    for (int nf = 0; nf < 4; nf++)
        #pragma unroll
        for (int i = 0; i < 4; i++) acc[nf][i] = 0.0f;

#define ISSUE2(kk, slot) { \
    int kc = (kk); \
    if (kc < KNBR) { \
        int r0 = __ldg(nbrp0 + kc); \
        int r1 = __ldg(nbrp1 + kc); \
        cp16(stg + (slot) * 1024 + lane * 16,       hBc + ((size_t)r0 << 6)); \
        cp16(stg + (slot) * 1024 + 512 + lane * 16, hBc + ((size_t)r1 << 6)); \
    } \
    cp_commit(); }

    ISSUE2(0, 0); ISSUE2(1, 1); ISSUE2(2, 2); ISSUE2(3, 3); ISSUE2(4, 4);
    int su = 0, si = 5;
    #pragma unroll 1
    for (int k = 0; k < KNBR; k++) {
        ISSUE2(k + 5, si);
        cp_wait5();
        uint4 A0 = stgv[su * 64 + lane];
        uint4 A1 = stgv[su * 64 + 32 + lane];
        #pragma unroll
        for (int nf = 0; nf < 4; nf++) {
            uint4 W = __ldg(w2v + ((k * 32 + nf * 8 + g) << 2) + c4);
            mma_f16(acc[nf], A0.x, A1.x, A0.y, A1.y, W.x, W.y);
            mma_f16(acc[nf], A0.z, A1.z, A0.w, A1.w, W.z, W.w);
        }
        if (++su == 6) su = 0;
        if (++si == 6) si = 0;
    }
#undef ISSUE2

    // Epilogue: point branch + fuse; write both output copies.
    {
        int n0 = nbase + warp * 16 + g;
        float z00 = zf[n0 * 3], z01 = zf[n0 * 3 + 1], z02 = zf[n0 * 3 + 2];
        float z10 = zf[(n0 + 8) * 3], z11 = zf[(n0 + 8) * 3 + 1], z12 = zf[(n0 + 8) * 3 + 2];
        #pragma unroll
        for (int nf = 0; nf < 4; nf++) {
            int o0 = nf * 8 + 2 * c4;
            float w0a = mw_s[o0],     w1a = mw_s[32 + o0],     w2a = mw_s[64 + o0];
            float w0b = mw_s[o0 + 1], w1b = mw_s[32 + o0 + 1], w2b = mw_s[64 + o0 + 1];
            float sA0 = pA[o0], sB0 = pB[o0], sA1 = pA[o0 + 1], sB1 = pB[o0 + 1];

            float d0 = z00 * w0a + z01 * w1a + z02 * w2a;
            float d1 = z00 * w0b + z01 * w1b + z02 * w2b;
            float e0 = z10 * w0a + z11 * w1a + z12 * w2a;
            float e1 = z10 * w0b + z11 * w1b + z12 * w2b;

            float2 lo, hi;
            lo.x = acc[nf][0] + fmaxf(d0 * sA0 + sB0, 0.0f);
            lo.y = acc[nf][1] + fmaxf(d1 * sA1 + sB1, 0.0f);
            hi.x = acc[nf][2] + fmaxf(e0 * sA0 + sB0, 0.0f);
            hi.y = acc[nf][3] + fmaxf(e1 * sA1 + sB1, 0.0f);

            size_t half = (size_t)N_NODES * FOUT;
            *(float2*)(out + (size_t)n0 * FOUT + o0)              = lo;
            *(float2*)(out + half + (size_t)n0 * FOUT + o0)       = lo;
            *(float2*)(out + (size_t)(n0 + 8) * FOUT + o0)        = hi;
            *(float2*)(out + half + (size_t)(n0 + 8) * FOUT + o0) = hi;
        }
    }
}

// ---------------------------------------------------------------------------

extern "C" void kernel_launch(void* const* d_in, const int* in_sizes, int n_in,
                              void* d_out, int out_size) {
    (void)in_sizes; (void)n_in; (void)out_size;
    const float* x    = (const float*)d_in[0];
    const float* z    = (const float*)d_in[1];
    const int*   nbr  = (const int*)  d_in[2];
    const float* w1   = (const float*)d_in[3];
    const float* bg   = (const float*)d_in[4];
    const float* bb   = (const float*)d_in[5];
    const float* bm   = (const float*)d_in[6];
    const float* bv   = (const float*)d_in[7];
    const float* w2   = (const float*)d_in[8];
    const float* mlpw = (const float*)d_in[9];
    const float* mlpb = (const float*)d_in[10];
    const float* mg   = (const float*)d_in[11];
    const float* mb2  = (const float*)d_in[12];
    const float* mm   = (const float*)d_in[13];
    const float* mv   = (const float*)d_in[14];
    float* out = (float*)d_out;

    cudaFuncSetAttribute(stage1_kernel, cudaFuncAttributeMaxDynamicSharedMemorySize, S1_SMEM);
    cudaFuncSetAttribute(stage2_kernel, cudaFuncAttributeMaxDynamicSharedMemorySize, S2_SMEM);

    stage1_kernel<<<NCHUNKS, 512, S1_SMEM>>>(x, nbr, w1, w2, bg, bb, bm, bv);
    stage2_kernel<<<NCHUNKS, 512, S2_SMEM>>>(nbr, z, mlpw, mlpb, mg, mb2, mm, mv, out);
}